// round 5
// baseline (speedup 1.0000x reference)
#include <cuda_runtime.h>
#include <math.h>

#define N_CLUS 64
#define C_DIM 768
#define B_DIM 8
#define H_IN 32
#define HW 1024                          // 32*32
#define OUT_HW 512
#define PLANE (OUT_HW * OUT_HW)          // 262144
#define NPIX (B_DIM * HW)                // 8192
#define RES_ELEMS ((size_t)B_DIM * N_CLUS * PLANE)   // 134217728
#define CODE_ELEMS ((size_t)B_DIM * C_DIM * HW)      // 6291456
#define KC 32

#define SIM_BLOCKS 128
#define ZERO_BLOCKS 1792
#define COPY_BLOCKS 128
#define A_BLOCKS (SIM_BLOCKS + ZERO_BLOCKS + COPY_BLOCKS)
// zero region = floats [1, 1+RES_ELEMS) of out. Head scalars 1,2,3; aligned
// float4 span floats [4, 134217728) = 33554431 float4s; tail scalar 134217728.
#define NQ4 33554431LL

__device__ int   g_assign[NPIX];
__device__ float g_maxcos[NPIX];

// ---------------------------------------------------------------------------
// Kernel A (block-specialized fusion):
//   blocks [0,128):        norms + sims + argmax (64 px x 64 clusters each)
//   blocks [128,1920):     float4 streaming zero-fill of resized region
//   blocks [1920,2048):    code passthrough copy
// Sim smem kept to ~17KB so zero blocks co-reside at 5+ blocks/SM.
// ---------------------------------------------------------------------------
__global__ __launch_bounds__(256) void fusedA(const float* __restrict__ code,
                                              const float* __restrict__ clusters,
                                              float* __restrict__ out) {
    const int tid = threadIdx.x;
    const int blk = blockIdx.x;

    if (blk >= SIM_BLOCKS) {
        if (blk < SIM_BLOCKS + ZERO_BLOCKS) {
            // ---- dense zero-fill, 16B-aligned streaming stores ----
            const int id = blk - SIM_BLOCKS;
            float4* o4 = (float4*)out;          // out is 16B aligned
            const float4 z = make_float4(0.f, 0.f, 0.f, 0.f);
            for (long long q = (long long)id * 256 + tid; q < NQ4;
                 q += (long long)ZERO_BLOCKS * 256)
                __stcs(&o4[1 + q], z);          // floats [4, 134217728)
            if (id == 0 && tid < 4)             // edge scalars
                out[(tid == 3) ? 134217728u : (1u + tid)] = 0.f;
        } else {
            // ---- code passthrough (dst 4B-aligned only; scalar stores) ----
            const int id = blk - SIM_BLOCKS - ZERO_BLOCKS;
            float* dst = out + 1 + RES_ELEMS;
            for (long long i = (long long)id * 256 + tid; i < (long long)CODE_ELEMS;
                 i += (long long)COPY_BLOCKS * 256)
                dst[i] = __ldg(code + i);
        }
        return;
    }

    // ================= sim branch =================
    __shared__ __align__(16) float codeS[KC][64];        // 8KB
    __shared__ __align__(16) float clusG[16][132];       // [ng][c*4+j], pad->132
    __shared__ float sinv[N_CLUS];

    const int wid = tid >> 5;
    const int lid = tid & 31;

    // ---- cluster inverse norms: warp w handles rows 8w..8w+7, lane-strided
    //      (coalesced) loads + shfl reduce. No L1tex jam. ----
    {
#pragma unroll
        for (int q = 0; q < 8; ++q) {
            const int n = wid * 8 + q;
            const float* cr = clusters + n * C_DIM;
            float s = 0.f;
#pragma unroll
            for (int i = 0; i < C_DIM / 32; ++i) {
                float v = __ldg(cr + lid + i * 32);
                s = fmaf(v, v, s);
            }
#pragma unroll
            for (int o = 16; o > 0; o >>= 1) s += __shfl_xor_sync(0xffffffffu, s, o);
            if (lid == 0) sinv[n] = 1.f / fmaxf(sqrtf(s), 1e-12f);
        }
    }
    __syncthreads();

    const int b = blk >> 4;                  // 16 blocks per image
    const int hwbase = (blk & 15) * 64;
    const int pid = tid >> 4;                // pixel quad: px 4*pid..4*pid+3
    const int ng = tid & 15;                 // cluster group: n = 4*ng..4*ng+3
    const float* codeb = code + (size_t)b * C_DIM * HW + hwbase;

    float acc[4][4];                         // [j cluster][p pixel]
#pragma unroll
    for (int j = 0; j < 4; ++j)
#pragma unroll
        for (int p = 0; p < 4; ++p) acc[j][p] = 0.f;
    float ssq[4] = {0.f, 0.f, 0.f, 0.f};

    for (int c0 = 0; c0 < C_DIM; c0 += KC) {
#pragma unroll
        for (int k = 0; k < 8; ++k) {        // stage code [KC][64], coalesced
            int idx = tid + k * 256;
            int c = idx >> 6, px = idx & 63;
            codeS[c][px] = codeb[(size_t)(c0 + c) * HW + px];
        }
#pragma unroll
        for (int k = 0; k < 8; ++k) {        // stage normed clusters as [ng][c][j]
            int idx = tid + k * 256;
            int g = idx >> 7, r = idx & 127;
            int j = r & 3, c = r >> 2;
            int n = g * 4 + j;
            clusG[g][c * 4 + j] = clusters[n * C_DIM + c0 + c] * sinv[n];
        }
        __syncthreads();

#pragma unroll 4
        for (int c = 0; c < KC; ++c) {
            float4 a = *(const float4*)&codeS[c][4 * pid];    // half-warp bcast
            float4 bv = *(const float4*)&clusG[ng][4 * c];    // 1 LDS.128
            if (ng == 0) {                   // fold feature sumsq into pass
                ssq[0] = fmaf(a.x, a.x, ssq[0]);
                ssq[1] = fmaf(a.y, a.y, ssq[1]);
                ssq[2] = fmaf(a.z, a.z, ssq[2]);
                ssq[3] = fmaf(a.w, a.w, ssq[3]);
            }
            acc[0][0] = fmaf(a.x, bv.x, acc[0][0]);
            acc[0][1] = fmaf(a.y, bv.x, acc[0][1]);
            acc[0][2] = fmaf(a.z, bv.x, acc[0][2]);
            acc[0][3] = fmaf(a.w, bv.x, acc[0][3]);
            acc[1][0] = fmaf(a.x, bv.y, acc[1][0]);
            acc[1][1] = fmaf(a.y, bv.y, acc[1][1]);
            acc[1][2] = fmaf(a.z, bv.y, acc[1][2]);
            acc[1][3] = fmaf(a.w, bv.y, acc[1][3]);
            acc[2][0] = fmaf(a.x, bv.z, acc[2][0]);
            acc[2][1] = fmaf(a.y, bv.z, acc[2][1]);
            acc[2][2] = fmaf(a.z, bv.z, acc[2][2]);
            acc[2][3] = fmaf(a.w, bv.z, acc[2][3]);
            acc[3][0] = fmaf(a.x, bv.w, acc[3][0]);
            acc[3][1] = fmaf(a.y, bv.w, acc[3][1]);
            acc[3][2] = fmaf(a.z, bv.w, acc[3][2]);
            acc[3][3] = fmaf(a.w, bv.w, acc[3][3]);
        }
        __syncthreads();
    }

    // per-pixel argmax: thread-local over 4 clusters, then shfl tree over the
    // 16-lane group (ng). Higher lane == higher n, so strict '>' when taking
    // the incoming value preserves first-max (lowest n) tiebreak.
#pragma unroll
    for (int p = 0; p < 4; ++p) {
        float mv = acc[0][p];
        int mn = ng * 4;
#pragma unroll
        for (int j = 1; j < 4; ++j)
            if (acc[j][p] > mv) { mv = acc[j][p]; mn = ng * 4 + j; }
#pragma unroll
        for (int off = 8; off > 0; off >>= 1) {
            float ov = __shfl_down_sync(0xffffffffu, mv, off, 16);
            int   on = __shfl_down_sync(0xffffffffu, mn, off, 16);
            if (ov > mv) { mv = ov; mn = on; }
        }
        if (ng == 0) {
            const int gp = blk * 64 + 4 * pid + p;   // b*1024 + hw index
            g_assign[gp] = mn;
            g_maxcos[gp] = mv / fmaxf(sqrtf(ssq[p]), 1e-12f);
        }
    }
}

// ---------------------------------------------------------------------------
// Kernel B: sparse bilinear scatter (<=4 nonzeros per output (y,x)) + loss.
// Grid: 4096 blocks = (b=8, y=512) x 512 threads (one x each).
// Block 4096 = deterministic loss reduction.
// ---------------------------------------------------------------------------
__global__ __launch_bounds__(512) void scatterB(float* __restrict__ out) {
    const int blk = blockIdx.x;
    if (blk == B_DIM * OUT_HW) {             // loss block
        __shared__ float red[512];
        float s = 0.f;
        for (int i = threadIdx.x; i < NPIX; i += 512) s += g_maxcos[i];
        red[threadIdx.x] = s;
        __syncthreads();
        for (int o = 256; o > 0; o >>= 1) {
            if (threadIdx.x < o) red[threadIdx.x] += red[threadIdx.x + o];
            __syncthreads();
        }
        if (threadIdx.x == 0) out[0] = -red[0] / (float)NPIX;
        return;
    }

    const int b = blk >> 9;
    const int y = blk & 511;
    const float fy = (y + 0.5f) * 0.0625f - 0.5f;
    const float y0f = floorf(fy);
    const float wy1 = fy - y0f;
    const float wy0 = 1.f - wy1;
    const int y0 = (int)y0f;
    const int ylo = max(y0, 0), yhi = min(y0 + 1, H_IN - 1);
    const int* arow0 = g_assign + b * HW + ylo * H_IN;
    const int* arow1 = g_assign + b * HW + yhi * H_IN;
    float* ob = out + 1 + (size_t)b * N_CLUS * PLANE + (size_t)y * OUT_HW;

    const int x = threadIdx.x;               // warp => consecutive x, coalesced
    const float fx = (x + 0.5f) * 0.0625f - 0.5f;
    const float x0f = floorf(fx);
    const float wx1 = fx - x0f;
    const float wx0 = 1.f - wx1;
    const int x0 = (int)x0f;
    const int xlo = max(x0, 0), xhi = min(x0 + 1, H_IN - 1);

    int n[4];
    float w[4];
    n[0] = __ldg(arow0 + xlo); w[0] = wy0 * wx0;
    n[1] = __ldg(arow0 + xhi); w[1] = wy0 * wx1;
    n[2] = __ldg(arow1 + xlo); w[2] = wy1 * wx0;
    n[3] = __ldg(arow1 + xhi); w[3] = wy1 * wx1;

    // merge duplicate cluster ids (each (b,n,y,x) written by one thread)
    bool v[4] = {true, true, true, true};
#pragma unroll
    for (int i = 1; i < 4; ++i)
#pragma unroll
        for (int j = 0; j < i; ++j)
            if (v[i] && v[j] && n[i] == n[j]) { w[j] += w[i]; v[i] = false; }

#pragma unroll
    for (int i = 0; i < 4; ++i)
        if (v[i]) ob[(size_t)n[i] * PLANE + x] = w[i];
}

// ---------------------------------------------------------------------------
// out layout = [loss(1)] [resized(134217728)] [code(6291456)]
// ---------------------------------------------------------------------------
extern "C" void kernel_launch(void* const* d_in, const int* in_sizes, int n_in,
                              void* d_out, int out_size) {
    const float* code = (const float*)d_in[0];
    const float* clusters = (const float*)d_in[1];
    float* out = (float*)d_out;

    fusedA<<<A_BLOCKS, 256>>>(code, clusters, out);
    scatterB<<<B_DIM * OUT_HW + 1, 512>>>(out);
}